// round 1
// baseline (speedup 1.0000x reference)
#include <cuda_runtime.h>
#include <math.h>

#define Bn 16
#define Cch 128
#define HWs 3136
#define Rr 16
#define MOc 256
#define CHUNK 8

__device__ float g_ctx[Bn * Cch];
__device__ float g_a[Bn * MOc];

// ---------------- Kernel 1: global-context attention pooling ----------------
__global__ void __launch_bounds__(1024) gc_ctx_kernel(const float* __restrict__ x,
                                                      const float* __restrict__ w_mask,
                                                      const float* __restrict__ b_mask) {
    __shared__ float s_att[HWs];
    __shared__ float s_wm[Cch];
    __shared__ float s_red[32];
    __shared__ float s_scalar;

    int b = blockIdx.x;
    int tid = threadIdx.x;
    const float* xb = x + (size_t)b * Cch * HWs;

    if (tid < Cch) s_wm[tid] = w_mask[tid];
    __syncthreads();

    int s0 = tid, s1 = tid + 1024, s2 = tid + 2048, s3 = tid + 3072;
    bool v3 = (s3 < HWs);

    float m0 = 0.f, m1 = 0.f, m2 = 0.f, m3 = 0.f;
    for (int c = 0; c < Cch; c++) {
        const float* xc = xb + c * HWs;
        float wm = s_wm[c];
        m0 = fmaf(xc[s0], wm, m0);
        m1 = fmaf(xc[s1], wm, m1);
        m2 = fmaf(xc[s2], wm, m2);
        if (v3) m3 = fmaf(xc[s3], wm, m3);
    }
    float bm = b_mask[0];
    m0 += bm; m1 += bm; m2 += bm; m3 += bm;

    // ---- block max ----
    float mx = fmaxf(fmaxf(m0, m1), m2);
    if (v3) mx = fmaxf(mx, m3);
    #pragma unroll
    for (int o = 16; o > 0; o >>= 1) mx = fmaxf(mx, __shfl_xor_sync(0xffffffffu, mx, o));
    if ((tid & 31) == 0) s_red[tid >> 5] = mx;
    __syncthreads();
    if (tid < 32) {
        float v = s_red[tid];
        #pragma unroll
        for (int o = 16; o > 0; o >>= 1) v = fmaxf(v, __shfl_xor_sync(0xffffffffu, v, o));
        if (tid == 0) s_scalar = v;
    }
    __syncthreads();
    float gmax = s_scalar;

    // ---- exp + block sum ----
    float e0 = expf(m0 - gmax);
    float e1 = expf(m1 - gmax);
    float e2 = expf(m2 - gmax);
    float e3 = v3 ? expf(m3 - gmax) : 0.f;
    float sm = e0 + e1 + e2 + e3;
    #pragma unroll
    for (int o = 16; o > 0; o >>= 1) sm += __shfl_xor_sync(0xffffffffu, sm, o);
    if ((tid & 31) == 0) s_red[tid >> 5] = sm;
    __syncthreads();
    if (tid < 32) {
        float v = s_red[tid];
        #pragma unroll
        for (int o = 16; o > 0; o >>= 1) v += __shfl_xor_sync(0xffffffffu, v, o);
        if (tid == 0) s_scalar = v;
    }
    __syncthreads();
    float inv = 1.f / s_scalar;

    s_att[s0] = e0 * inv;
    s_att[s1] = e1 * inv;
    s_att[s2] = e2 * inv;
    if (v3) s_att[s3] = e3 * inv;
    __syncthreads();

    // ---- ctx[c] = sum_s x[b,c,s] * att[s], warp per channel ----
    int warp = tid >> 5, lane = tid & 31;
    for (int c = warp; c < Cch; c += 32) {
        const float* xc = xb + c * HWs;
        float p = 0.f;
        for (int s = lane; s < HWs; s += 32) p = fmaf(xc[s], s_att[s], p);
        #pragma unroll
        for (int o = 16; o > 0; o >>= 1) p += __shfl_xor_sync(0xffffffffu, p, o);
        if (lane == 0) g_ctx[b * Cch + c] = p;
    }
}

// ---------------- Kernel 2: bottleneck transform -> gates a[b,256] ----------------
__global__ void __launch_bounds__(256) transform_kernel(const float* __restrict__ w1,
                                                        const float* __restrict__ b1,
                                                        const float* __restrict__ ln_g,
                                                        const float* __restrict__ ln_b,
                                                        const float* __restrict__ w2,
                                                        const float* __restrict__ b2) {
    __shared__ float s_ctx[Cch];
    __shared__ float s_t[Rr];
    int b = blockIdx.x;
    int tid = threadIdx.x;
    if (tid < Cch) s_ctx[tid] = g_ctx[b * Cch + tid];
    __syncthreads();
    if (tid < Rr) {
        float acc = b1[tid];
        const float* wr = w1 + tid * Cch;
        for (int c = 0; c < Cch; c++) acc = fmaf(s_ctx[c], wr[c], acc);
        s_t[tid] = acc;
    }
    __syncthreads();
    if (tid == 0) {
        float mu = 0.f;
        #pragma unroll
        for (int r = 0; r < Rr; r++) mu += s_t[r];
        mu *= (1.f / Rr);
        float var = 0.f;
        #pragma unroll
        for (int r = 0; r < Rr; r++) { float d = s_t[r] - mu; var = fmaf(d, d, var); }
        var *= (1.f / Rr);
        float invs = rsqrtf(var + 1e-5f);
        #pragma unroll
        for (int r = 0; r < Rr; r++) {
            float v = (s_t[r] - mu) * invs * ln_g[r] + ln_b[r];
            s_t[r] = fmaxf(v, 0.f);
        }
    }
    __syncthreads();
    {
        float acc = b2[tid];
        const float* wr = w2 + tid * Rr;
        #pragma unroll
        for (int r = 0; r < Rr; r++) acc = fmaf(s_t[r], wr[r], acc);
        g_a[b * MOc + tid] = 1.f / (1.f + expf(-acc));
    }
}

// ---------------- Kernel 3: per-sample 3x3 conv with fused weight generation ----------------
// grid: (28 spatial row-pair tiles, 2 cout tiles of 64, 16 batch), 256 threads
__global__ void __launch_bounds__(256) conv_kernel(const float* __restrict__ x,
                                                   const float* __restrict__ w_fc,
                                                   const float* __restrict__ b_fc,
                                                   float* __restrict__ out) {
    __shared__ float s_in[CHUNK][4][58];
    __shared__ __align__(16) float s_w[CHUNK * 9 * 64];  // [cin_l*9+k][cout_local]

    int tid = threadIdx.x;
    int st = blockIdx.x;          // 0..27 -> output rows 2*st, 2*st+1
    int cout_base = blockIdx.y * 64;
    int b = blockIdx.z;

    int y_base = st * 2;
    int ct = tid & 15;            // cout sub-tile: couts cout_base + 4*ct .. +3
    int pg = tid >> 4;            // pixel group 0..15
    int row_loc = pg >> 3;        // 0/1
    int col0 = (pg & 7) * 7;      // 7 consecutive output cols

    const float* xb = x + (size_t)b * Cch * HWs;
    const float* ab = g_a + b * MOc;

    float acc[4][7];
    #pragma unroll
    for (int j = 0; j < 4; j++)
        #pragma unroll
        for (int p = 0; p < 7; p++) acc[j][p] = 0.f;

    for (int chunk = 0; chunk < Cch / CHUNK; chunk++) {
        __syncthreads();
        // load input halo tile: CHUNK channels x 4 rows x 58 cols
        for (int i = tid; i < CHUNK * 4 * 58; i += 256) {
            int col = i % 58;
            int rest = i / 58;
            int r = rest & 3;
            int cin_l = rest >> 2;
            int gy = y_base + r - 1;
            int gx = col - 1;
            float v = 0.f;
            if ((unsigned)gy < 56u && (unsigned)gx < 56u)
                v = xb[(chunk * CHUNK + cin_l) * HWs + gy * 56 + gx];
            ((float*)s_in)[i] = v;
        }
        // generate + load weights: CHUNK*9 k-slices x 64 couts
        for (int i = tid; i < CHUNK * 9 * 64; i += 256) {
            int co_l = i & 63;
            int kidx = i >> 6;
            int cin_l = kidx / 9;
            int k = kidx - cin_l * 9;
            int cin_g = chunk * CHUNK + cin_l;
            int co_g = cout_base + co_l;
            int gidx = co_g * 1152 + cin_g * 9 + k;
            float aval = ab[2 * co_g + (cin_g >> 6)];
            s_w[i] = fmaf(aval, w_fc[gidx], b_fc[gidx]);
        }
        __syncthreads();

        #pragma unroll
        for (int cin_l = 0; cin_l < CHUNK; cin_l++) {
            #pragma unroll
            for (int ky = 0; ky < 3; ky++) {
                float xin[9];
                #pragma unroll
                for (int q = 0; q < 9; q++) xin[q] = s_in[cin_l][row_loc + ky][col0 + q];
                #pragma unroll
                for (int kx = 0; kx < 3; kx++) {
                    float4 wv = *(const float4*)&s_w[((cin_l * 9 + ky * 3 + kx) << 6) + (ct << 2)];
                    #pragma unroll
                    for (int p = 0; p < 7; p++) {
                        acc[0][p] = fmaf(wv.x, xin[p + kx], acc[0][p]);
                        acc[1][p] = fmaf(wv.y, xin[p + kx], acc[1][p]);
                        acc[2][p] = fmaf(wv.z, xin[p + kx], acc[2][p]);
                        acc[3][p] = fmaf(wv.w, xin[p + kx], acc[3][p]);
                    }
                }
            }
        }
    }

    // epilogue
    int oy = y_base + row_loc;
    float* ob = out + ((size_t)b * Cch + cout_base) * HWs;
    #pragma unroll
    for (int j = 0; j < 4; j++) {
        float* orow = ob + (ct * 4 + j) * HWs + oy * 56 + col0;
        #pragma unroll
        for (int p = 0; p < 7; p++) orow[p] = acc[j][p];
    }
}

extern "C" void kernel_launch(void* const* d_in, const int* in_sizes, int n_in,
                              void* d_out, int out_size) {
    const float* x      = (const float*)d_in[0];
    const float* w_mask = (const float*)d_in[1];
    const float* b_mask = (const float*)d_in[2];
    const float* w1     = (const float*)d_in[3];
    const float* b1     = (const float*)d_in[4];
    const float* ln_g   = (const float*)d_in[5];
    const float* ln_b   = (const float*)d_in[6];
    const float* w2     = (const float*)d_in[7];
    const float* b2     = (const float*)d_in[8];
    const float* w_fc   = (const float*)d_in[9];
    const float* b_fc   = (const float*)d_in[10];
    float* out = (float*)d_out;

    gc_ctx_kernel<<<Bn, 1024>>>(x, w_mask, b_mask);
    transform_kernel<<<Bn, 256>>>(w1, b1, ln_g, ln_b, w2, b2);
    conv_kernel<<<dim3(28, 2, Bn), 256>>>(x, w_fc, b_fc, out);
}

// round 2
// speedup vs baseline: 1.0110x; 1.0110x over previous
#include <cuda_runtime.h>
#include <math.h>

#define Bn 16
#define Cch 128
#define HWs 3136
#define Rr 16
#define MOc 256
#define CHUNK 8

__device__ float g_ctx[Bn * Cch];
__device__ float g_a[Bn * MOc];
__device__ float g_mask[Bn * HWs];
__device__ float g_att[Bn * HWs];

#define FMA2(acc, w, xv) \
    asm("fma.rn.f32x2 %0, %1, %2, %0;" : "+l"(acc) : "l"(w), "l"(xv))

// ---------------- Kernel A: mask[b,s] = sum_c x[b,c,s]*w_mask[c] + b_mask ----------------
__global__ void __launch_bounds__(448) mask_kernel(const float* __restrict__ x,
                                                   const float* __restrict__ w_mask,
                                                   const float* __restrict__ b_mask) {
    __shared__ float s_wm[Cch];
    int tid = threadIdx.x;
    int b = blockIdx.y;
    int s = blockIdx.x * 448 + tid;
    if (tid < Cch) s_wm[tid] = w_mask[tid];
    __syncthreads();
    const float* xb = x + (size_t)b * Cch * HWs + s;
    float m = 0.f;
    #pragma unroll 8
    for (int c = 0; c < Cch; c++) m = fmaf(xb[c * HWs], s_wm[c], m);
    g_mask[b * HWs + s] = m + b_mask[0];
}

// ---------------- Kernel B: softmax over spatial dim per batch ----------------
__global__ void __launch_bounds__(1024) softmax_kernel() {
    __shared__ float s_red[32];
    __shared__ float s_scalar;
    int b = blockIdx.x;
    int tid = threadIdx.x;
    const float* mb = g_mask + b * HWs;

    int s0 = tid, s1 = tid + 1024, s2 = tid + 2048, s3 = tid + 3072;
    bool v3 = (s3 < HWs);
    float m0 = mb[s0], m1 = mb[s1], m2 = mb[s2], m3 = v3 ? mb[s3] : -1e30f;

    float mx = fmaxf(fmaxf(m0, m1), fmaxf(m2, m3));
    #pragma unroll
    for (int o = 16; o > 0; o >>= 1) mx = fmaxf(mx, __shfl_xor_sync(0xffffffffu, mx, o));
    if ((tid & 31) == 0) s_red[tid >> 5] = mx;
    __syncthreads();
    if (tid < 32) {
        float v = s_red[tid];
        #pragma unroll
        for (int o = 16; o > 0; o >>= 1) v = fmaxf(v, __shfl_xor_sync(0xffffffffu, v, o));
        if (tid == 0) s_scalar = v;
    }
    __syncthreads();
    float gmax = s_scalar;

    float e0 = expf(m0 - gmax), e1 = expf(m1 - gmax), e2 = expf(m2 - gmax);
    float e3 = v3 ? expf(m3 - gmax) : 0.f;
    float sm = e0 + e1 + e2 + e3;
    #pragma unroll
    for (int o = 16; o > 0; o >>= 1) sm += __shfl_xor_sync(0xffffffffu, sm, o);
    if ((tid & 31) == 0) s_red[tid >> 5] = sm;
    __syncthreads();
    if (tid < 32) {
        float v = s_red[tid];
        #pragma unroll
        for (int o = 16; o > 0; o >>= 1) v += __shfl_xor_sync(0xffffffffu, v, o);
        if (tid == 0) s_scalar = v;
    }
    __syncthreads();
    float inv = 1.f / s_scalar;

    float* ab = g_att + b * HWs;
    ab[s0] = e0 * inv;
    ab[s1] = e1 * inv;
    ab[s2] = e2 * inv;
    if (v3) ab[s3] = e3 * inv;
}

// ---------------- Kernel C: ctx[b,c] = sum_s x[b,c,s]*att[b,s] ----------------
__global__ void __launch_bounds__(512) ctx_kernel(const float* __restrict__ x) {
    __shared__ float s_att[HWs];
    int tid = threadIdx.x;
    int b = blockIdx.y;
    int c_base = blockIdx.x * 16;
    const float* ab = g_att + b * HWs;
    for (int i = tid; i < HWs; i += 512) s_att[i] = ab[i];
    __syncthreads();
    int warp = tid >> 5, lane = tid & 31;
    int c = c_base + warp;
    const float* xc = x + ((size_t)b * Cch + c) * HWs;
    float p = 0.f;
    for (int s = lane; s < HWs; s += 32) p = fmaf(xc[s], s_att[s], p);
    #pragma unroll
    for (int o = 16; o > 0; o >>= 1) p += __shfl_xor_sync(0xffffffffu, p, o);
    if (lane == 0) g_ctx[b * Cch + c] = p;
}

// ---------------- Kernel 2: bottleneck transform -> gates a[b,256] ----------------
__global__ void __launch_bounds__(256) transform_kernel(const float* __restrict__ w1,
                                                        const float* __restrict__ b1,
                                                        const float* __restrict__ ln_g,
                                                        const float* __restrict__ ln_b,
                                                        const float* __restrict__ w2,
                                                        const float* __restrict__ b2) {
    __shared__ float s_ctx[Cch];
    __shared__ float s_t[Rr];
    int b = blockIdx.x;
    int tid = threadIdx.x;
    if (tid < Cch) s_ctx[tid] = g_ctx[b * Cch + tid];
    __syncthreads();
    if (tid < Rr) {
        float acc = b1[tid];
        const float* wr = w1 + tid * Cch;
        for (int c = 0; c < Cch; c++) acc = fmaf(s_ctx[c], wr[c], acc);
        s_t[tid] = acc;
    }
    __syncthreads();
    if (tid == 0) {
        float mu = 0.f;
        #pragma unroll
        for (int r = 0; r < Rr; r++) mu += s_t[r];
        mu *= (1.f / Rr);
        float var = 0.f;
        #pragma unroll
        for (int r = 0; r < Rr; r++) { float d = s_t[r] - mu; var = fmaf(d, d, var); }
        var *= (1.f / Rr);
        float invs = rsqrtf(var + 1e-5f);
        #pragma unroll
        for (int r = 0; r < Rr; r++) {
            float v = (s_t[r] - mu) * invs * ln_g[r] + ln_b[r];
            s_t[r] = fmaxf(v, 0.f);
        }
    }
    __syncthreads();
    {
        float acc = b2[tid];
        const float* wr = w2 + tid * Rr;
        #pragma unroll
        for (int r = 0; r < Rr; r++) acc = fmaf(s_t[r], wr[r], acc);
        g_a[b * MOc + tid] = 1.f / (1.f + expf(-acc));
    }
}

// ---------------- Kernel 3: per-sample 3x3 conv, FFMA2 packed over cout pairs ----------------
// grid: (28 spatial row-pair tiles, 2 cout tiles of 64, 16 batch), 256 threads
__global__ void __launch_bounds__(256) conv_kernel(const float* __restrict__ x,
                                                   const float* __restrict__ w_fc,
                                                   const float* __restrict__ b_fc,
                                                   float* __restrict__ out) {
    __shared__ __align__(16) float2 s_in2[CHUNK][4][58];     // duplicated {v,v}
    __shared__ __align__(16) float s_w[CHUNK * 9 * 64];      // [cin_l*9+k][cout_local]

    int tid = threadIdx.x;
    int st = blockIdx.x;          // output rows 2*st, 2*st+1
    int cout_base = blockIdx.y * 64;
    int b = blockIdx.z;

    int y_base = st * 2;
    int ct = tid & 15;            // cout sub-tile: couts cout_base + 4*ct .. +3
    int pg = tid >> 4;            // pixel group 0..15
    int row_loc = pg >> 3;        // 0/1
    int col0 = (pg & 7) * 7;      // 7 consecutive output cols

    const float* xb = x + (size_t)b * Cch * HWs;
    const float* ab = g_a + b * MOc;

    unsigned long long acc01[7], acc23[7];
    #pragma unroll
    for (int p = 0; p < 7; p++) { acc01[p] = 0ull; acc23[p] = 0ull; }

    for (int chunk = 0; chunk < Cch / CHUNK; chunk++) {
        __syncthreads();
        // load input halo tile duplicated: CHUNK channels x 4 rows x 58 cols
        for (int i = tid; i < CHUNK * 4 * 58; i += 256) {
            int col = i % 58;
            int rest = i / 58;
            int r = rest & 3;
            int cin_l = rest >> 2;
            int gy = y_base + r - 1;
            int gx = col - 1;
            float v = 0.f;
            if ((unsigned)gy < 56u && (unsigned)gx < 56u)
                v = xb[(chunk * CHUNK + cin_l) * HWs + gy * 56 + gx];
            ((float2*)s_in2)[i] = make_float2(v, v);
        }
        // generate weights: CHUNK*9 k-slices x 64 couts
        for (int i = tid; i < CHUNK * 9 * 64; i += 256) {
            int co_l = i & 63;
            int kidx = i >> 6;
            int cin_l = kidx / 9;
            int k = kidx - cin_l * 9;
            int cin_g = chunk * CHUNK + cin_l;
            int co_g = cout_base + co_l;
            int gidx = co_g * 1152 + cin_g * 9 + k;
            float aval = ab[2 * co_g + (cin_g >> 6)];
            s_w[i] = fmaf(aval, w_fc[gidx], b_fc[gidx]);
        }
        __syncthreads();

        #pragma unroll
        for (int cin_l = 0; cin_l < CHUNK; cin_l++) {
            #pragma unroll
            for (int ky = 0; ky < 3; ky++) {
                unsigned long long xd[9];
                #pragma unroll
                for (int q = 0; q < 9; q++)
                    xd[q] = *(const unsigned long long*)&s_in2[cin_l][row_loc + ky][col0 + q];
                #pragma unroll
                for (int kx = 0; kx < 3; kx++) {
                    const unsigned long long* wp =
                        (const unsigned long long*)&s_w[((cin_l * 9 + ky * 3 + kx) << 6) + (ct << 2)];
                    unsigned long long w01 = wp[0];
                    unsigned long long w23 = wp[1];
                    #pragma unroll
                    for (int p = 0; p < 7; p++) {
                        FMA2(acc01[p], w01, xd[p + kx]);
                        FMA2(acc23[p], w23, xd[p + kx]);
                    }
                }
            }
        }
    }

    // epilogue: unpack f32x2 pairs
    int oy = y_base + row_loc;
    float* ob = out + ((size_t)b * Cch + cout_base + ct * 4) * HWs + oy * 56 + col0;
    #pragma unroll
    for (int p = 0; p < 7; p++) {
        float2 v01 = *(float2*)&acc01[p];
        float2 v23 = *(float2*)&acc23[p];
        ob[p] = v01.x;
        ob[HWs + p] = v01.y;
        ob[2 * HWs + p] = v23.x;
        ob[3 * HWs + p] = v23.y;
    }
}

extern "C" void kernel_launch(void* const* d_in, const int* in_sizes, int n_in,
                              void* d_out, int out_size) {
    const float* x      = (const float*)d_in[0];
    const float* w_mask = (const float*)d_in[1];
    const float* b_mask = (const float*)d_in[2];
    const float* w1     = (const float*)d_in[3];
    const float* b1     = (const float*)d_in[4];
    const float* ln_g   = (const float*)d_in[5];
    const float* ln_b   = (const float*)d_in[6];
    const float* w2     = (const float*)d_in[7];
    const float* b2     = (const float*)d_in[8];
    const float* w_fc   = (const float*)d_in[9];
    const float* b_fc   = (const float*)d_in[10];
    float* out = (float*)d_out;

    mask_kernel<<<dim3(7, Bn), 448>>>(x, w_mask, b_mask);
    softmax_kernel<<<Bn, 1024>>>();
    ctx_kernel<<<dim3(8, Bn), 512>>>(x);
    transform_kernel<<<Bn, 256>>>(w1, b1, ln_g, ln_b, w2, b2);
    conv_kernel<<<dim3(28, 2, Bn), 256>>>(x, w_fc, b_fc, out);
}

// round 4
// speedup vs baseline: 4.4193x; 4.3712x over previous
#include <cuda_runtime.h>
#include <cuda_bf16.h>
#include <math.h>
#include <stdint.h>

#define Bn 16
#define Cch 128
#define HWs 3136
#define Rr 16
#define MOc 256

// ---------------- device globals ----------------
__device__ float g_ctx[Bn * Cch];
__device__ float g_a[Bn * MOc];
__device__ float g_mask[Bn * HWs];
__device__ float g_att[Bn * HWs];
// per-(b,tap,chunk) weight tiles, plain row-major 128 cout x 64 cin bf16
__device__ __align__(16) __nv_bfloat16 g_wA_hi[16 * 18 * 8192];
__device__ __align__(16) __nv_bfloat16 g_wA_lo[16 * 18 * 8192];

// ---------------- PTX helpers (all target-portable, sm_80+) ----------------
__device__ __forceinline__ uint32_t smem_u32(const void* p) {
    uint32_t a;
    asm("{ .reg .u64 t; cvta.to.shared.u64 t, %1; cvt.u32.u64 %0, t; }" : "=r"(a) : "l"(p));
    return a;
}
__device__ __forceinline__ void ldsm4(uint32_t a, uint32_t* r) {
    asm volatile("ldmatrix.sync.aligned.m8n8.x4.shared.b16 {%0,%1,%2,%3}, [%4];"
                 : "=r"(r[0]), "=r"(r[1]), "=r"(r[2]), "=r"(r[3]) : "r"(a));
}
__device__ __forceinline__ void ldsm4b(uint32_t a, uint32_t* r0, uint32_t* r1) {
    asm volatile("ldmatrix.sync.aligned.m8n8.x4.shared.b16 {%0,%1,%2,%3}, [%4];"
                 : "=r"(r0[0]), "=r"(r0[1]), "=r"(r1[0]), "=r"(r1[1]) : "r"(a));
}
__device__ __forceinline__ void ldsm2(uint32_t a, uint32_t* r) {
    asm volatile("ldmatrix.sync.aligned.m8n8.x2.shared.b16 {%0,%1}, [%2];"
                 : "=r"(r[0]), "=r"(r[1]) : "r"(a));
}
__device__ __forceinline__ void mma16816(float* c, const uint32_t* a, const uint32_t* b) {
    asm volatile("mma.sync.aligned.m16n8k16.row.col.f32.bf16.bf16.f32 "
                 "{%0,%1,%2,%3}, {%4,%5,%6,%7}, {%8,%9}, {%0,%1,%2,%3};"
                 : "+f"(c[0]), "+f"(c[1]), "+f"(c[2]), "+f"(c[3])
                 : "r"(a[0]), "r"(a[1]), "r"(a[2]), "r"(a[3]), "r"(b[0]), "r"(b[1]));
}
__device__ __forceinline__ void cp16(uint32_t dst, const void* src) {
    asm volatile("cp.async.cg.shared.global [%0], [%1], 16;" :: "r"(dst), "l"(src));
}
#define CP_COMMIT() asm volatile("cp.async.commit_group;" ::: "memory")
#define CP_WAIT1() asm volatile("cp.async.wait_group 1;" ::: "memory")
#define CP_WAIT0() asm volatile("cp.async.wait_group 0;" ::: "memory")

// ---------------- Kernel A: mask ----------------
__global__ void __launch_bounds__(448) mask_kernel(const float* __restrict__ x,
                                                   const float* __restrict__ w_mask,
                                                   const float* __restrict__ b_mask) {
    __shared__ float s_wm[Cch];
    int tid = threadIdx.x;
    int b = blockIdx.y;
    int s = blockIdx.x * 448 + tid;
    if (tid < Cch) s_wm[tid] = w_mask[tid];
    __syncthreads();
    const float* xb = x + (size_t)b * Cch * HWs + s;
    float m = 0.f;
    #pragma unroll 8
    for (int c = 0; c < Cch; c++) m = fmaf(xb[c * HWs], s_wm[c], m);
    g_mask[b * HWs + s] = m + b_mask[0];
}

// ---------------- Kernel B: softmax ----------------
__global__ void __launch_bounds__(1024) softmax_kernel() {
    __shared__ float s_red[32];
    __shared__ float s_scalar;
    int b = blockIdx.x;
    int tid = threadIdx.x;
    const float* mb = g_mask + b * HWs;
    int s0 = tid, s1 = tid + 1024, s2 = tid + 2048, s3 = tid + 3072;
    bool v3 = (s3 < HWs);
    float m0 = mb[s0], m1 = mb[s1], m2 = mb[s2], m3 = v3 ? mb[s3] : -1e30f;
    float mx = fmaxf(fmaxf(m0, m1), fmaxf(m2, m3));
    #pragma unroll
    for (int o = 16; o > 0; o >>= 1) mx = fmaxf(mx, __shfl_xor_sync(0xffffffffu, mx, o));
    if ((tid & 31) == 0) s_red[tid >> 5] = mx;
    __syncthreads();
    if (tid < 32) {
        float v = s_red[tid];
        #pragma unroll
        for (int o = 16; o > 0; o >>= 1) v = fmaxf(v, __shfl_xor_sync(0xffffffffu, v, o));
        if (tid == 0) s_scalar = v;
    }
    __syncthreads();
    float gmax = s_scalar;
    float e0 = expf(m0 - gmax), e1 = expf(m1 - gmax), e2 = expf(m2 - gmax);
    float e3 = v3 ? expf(m3 - gmax) : 0.f;
    float sm = e0 + e1 + e2 + e3;
    #pragma unroll
    for (int o = 16; o > 0; o >>= 1) sm += __shfl_xor_sync(0xffffffffu, sm, o);
    if ((tid & 31) == 0) s_red[tid >> 5] = sm;
    __syncthreads();
    if (tid < 32) {
        float v = s_red[tid];
        #pragma unroll
        for (int o = 16; o > 0; o >>= 1) v += __shfl_xor_sync(0xffffffffu, v, o);
        if (tid == 0) s_scalar = v;
    }
    __syncthreads();
    float inv = 1.f / s_scalar;
    float* ab = g_att + b * HWs;
    ab[s0] = e0 * inv;
    ab[s1] = e1 * inv;
    ab[s2] = e2 * inv;
    if (v3) ab[s3] = e3 * inv;
}

// ---------------- Kernel C: ctx ----------------
__global__ void __launch_bounds__(512) ctx_kernel(const float* __restrict__ x) {
    __shared__ float s_att[HWs];
    int tid = threadIdx.x;
    int b = blockIdx.y;
    int c_base = blockIdx.x * 16;
    const float* ab = g_att + b * HWs;
    for (int i = tid; i < HWs; i += 512) s_att[i] = ab[i];
    __syncthreads();
    int warp = tid >> 5, lane = tid & 31;
    int c = c_base + warp;
    const float* xc = x + ((size_t)b * Cch + c) * HWs;
    float p = 0.f;
    for (int s = lane; s < HWs; s += 32) p = fmaf(xc[s], s_att[s], p);
    #pragma unroll
    for (int o = 16; o > 0; o >>= 1) p += __shfl_xor_sync(0xffffffffu, p, o);
    if (lane == 0) g_ctx[b * Cch + c] = p;
}

// ---------------- Kernel 2: transform -> gates ----------------
__global__ void __launch_bounds__(256) transform_kernel(const float* __restrict__ w1,
                                                        const float* __restrict__ b1,
                                                        const float* __restrict__ ln_g,
                                                        const float* __restrict__ ln_b,
                                                        const float* __restrict__ w2,
                                                        const float* __restrict__ b2) {
    __shared__ float s_ctx[Cch];
    __shared__ float s_t[Rr];
    int b = blockIdx.x;
    int tid = threadIdx.x;
    if (tid < Cch) s_ctx[tid] = g_ctx[b * Cch + tid];
    __syncthreads();
    if (tid < Rr) {
        float acc = b1[tid];
        const float* wr = w1 + tid * Cch;
        for (int c = 0; c < Cch; c++) acc = fmaf(s_ctx[c], wr[c], acc);
        s_t[tid] = acc;
    }
    __syncthreads();
    if (tid == 0) {
        float mu = 0.f;
        #pragma unroll
        for (int r = 0; r < Rr; r++) mu += s_t[r];
        mu *= (1.f / Rr);
        float var = 0.f;
        #pragma unroll
        for (int r = 0; r < Rr; r++) { float d = s_t[r] - mu; var = fmaf(d, d, var); }
        var *= (1.f / Rr);
        float invs = rsqrtf(var + 1e-5f);
        #pragma unroll
        for (int r = 0; r < Rr; r++) {
            float v = (s_t[r] - mu) * invs * ln_g[r] + ln_b[r];
            s_t[r] = fmaxf(v, 0.f);
        }
    }
    __syncthreads();
    {
        float acc = b2[tid];
        const float* wr = w2 + tid * Rr;
        #pragma unroll
        for (int r = 0; r < Rr; r++) acc = fmaf(s_t[r], wr[r], acc);
        g_a[b * MOc + tid] = 1.f / (1.f + expf(-acc));
    }
}

// ---------------- Kernel 3: generate bf16 hi/lo weight tiles ----------------
// grid 16*18 blocks (b, tap, chunk), 256 threads; tile = 128 cout x 64 cin
__global__ void __launch_bounds__(256) prepA_kernel(const float* __restrict__ w_fc,
                                                    const float* __restrict__ b_fc) {
    int p = blockIdx.x;
    int b = p / 18;
    int rem = p - b * 18;
    int tap = rem >> 1;
    int chunk = rem & 1;
    __nv_bfloat16* dh = g_wA_hi + (size_t)p * 8192;
    __nv_bfloat16* dl = g_wA_lo + (size_t)p * 8192;
    int tid = threadIdx.x;
    for (int e = tid; e < 8192; e += 256) {
        int co = e >> 6;
        int c = e & 63;
        int cin = chunk * 64 + c;
        int gidx = co * 1152 + cin * 9 + tap;
        float av = g_a[b * MOc + 2 * co + chunk];
        float w = fmaf(av, w_fc[gidx], b_fc[gidx]);
        __nv_bfloat16 hi = __float2bfloat16(w);
        __nv_bfloat16 lo = __float2bfloat16(w - __bfloat162float(hi));
        dh[e] = hi;
        dl[e] = lo;
    }
}

// ---------------- Kernel 4: HMMA implicit-GEMM conv ----------------
// grid (28 row-pair tiles, 16 batch), 256 threads (8 warps), 1 CTA/SM.
// smem: Xt_hi [232 rows x 72 bf16], Xt_lo same; A double buffer (hi+lo) stride-72.
#define XT_H       0
#define XT_L       33408
#define A_BASE     66816
#define A_BUF_SZ   36864      /* hi tile 18432 + lo tile 18432 */
#define SMEM_TOTAL 140544

__global__ void __launch_bounds__(256) conv_kernel(const float* __restrict__ x,
                                                   float* __restrict__ out) {
    extern __shared__ __align__(16) char smem[];
    uint32_t su = smem_u32(smem);
    int tid = threadIdx.x;
    int wid = tid >> 5;
    int lane = tid & 31;
    int t = blockIdx.x;
    int b = blockIdx.y;

    int grp = lane >> 3, lr = lane & 7;
    int m_base = (wid & 3) * 32;            // cout base for this warp
    int rr = wid >> 2;                      // output row within pair
    int n_base = rr * 56;

    // ldmatrix per-lane offsets (bytes); stride = 72 bf16 = 144 B
    uint32_t a_lane = (uint32_t)((((grp & 1) * 8 + lr) * 144) + ((grp >> 1) * 16));
    uint32_t b4_lane = (uint32_t)((((grp >> 1) * 8 + lr) * 144) + ((grp & 1) * 16));
    int l16 = lane & 15;
    uint32_t b2_lane = (uint32_t)(((l16 & 7) * 144) + (((l16 >> 3) & 1) * 16));

    float acc[2][7][4];
    #pragma unroll
    for (int mt = 0; mt < 2; mt++)
        #pragma unroll
        for (int nt = 0; nt < 7; nt++)
            #pragma unroll
            for (int e = 0; e < 4; e++) acc[mt][nt][e] = 0.f;

    // ---- issue A copy for s=0 ----
    {
        const char* sh = (const char*)(g_wA_hi + (size_t)(b * 18 + 0) * 8192);
        const char* sl = (const char*)(g_wA_lo + (size_t)(b * 18 + 0) * 8192);
        uint32_t dh = su + A_BASE;
        for (int i = tid; i < 1024; i += 256) {
            uint32_t doff = (uint32_t)((i >> 3) * 144 + (i & 7) * 16);
            cp16(dh + doff, sh + i * 16);
            cp16(dh + 18432 + doff, sl + i * 16);
        }
        CP_COMMIT();
    }

    for (int s = 0; s < 18; s++) {
        int chunk = (s >= 9) ? 1 : 0;
        int tap = s - chunk * 9;
        int ky = tap / 3;
        int kx = tap - ky * 3;
        int buf = s & 1;

        if (s < 17) {
            int s1 = s + 1;
            int ch1 = (s1 >= 9) ? 1 : 0;
            int tp1 = s1 - ch1 * 9;
            const char* sh = (const char*)(g_wA_hi + (size_t)(b * 18 + tp1 * 2 + ch1) * 8192);
            const char* sl = (const char*)(g_wA_lo + (size_t)(b * 18 + tp1 * 2 + ch1) * 8192);
            uint32_t dh = su + A_BASE + (buf ^ 1) * A_BUF_SZ;
            for (int i = tid; i < 1024; i += 256) {
                uint32_t doff = (uint32_t)((i >> 3) * 144 + (i & 7) * 16);
                cp16(dh + doff, sh + i * 16);
                cp16(dh + 18432 + doff, sl + i * 16);
            }
            CP_COMMIT();
            CP_WAIT1();
        } else {
            CP_WAIT0();
        }

        if (tap == 0) {
            // build Xt for this chunk: 232 pixel rows x 64 cins, split hi/lo
            __nv_bfloat16* xh = (__nv_bfloat16*)(smem + XT_H);
            __nv_bfloat16* xl = (__nv_bfloat16*)(smem + XT_L);
            for (int i = tid; i < 64 * 232; i += 256) {
                int cin = i / 232;
                int j = i - cin * 232;
                int r = j / 58;
                int c = j - r * 58;
                int gy = 2 * t + r - 1;
                int gx = c - 1;
                float v = 0.f;
                if ((unsigned)gy < 56u && (unsigned)gx < 56u)
                    v = x[((size_t)(b * Cch + chunk * 64 + cin)) * HWs + gy * 56 + gx];
                __nv_bfloat16 hi = __float2bfloat16(v);
                __nv_bfloat16 lo = __float2bfloat16(v - __bfloat162float(hi));
                xh[j * 72 + cin] = hi;
                xl[j * 72 + cin] = lo;
            }
        }
        __syncthreads();

        // ---- compute ----
        uint32_t AH = su + A_BASE + buf * A_BUF_SZ + (uint32_t)(m_base * 144) + a_lane;
        uint32_t AL = AH + 18432;
        uint32_t brow = (uint32_t)(((rr + ky) * 58 + kx) * 144);
        uint32_t XH = su + XT_H + brow;
        uint32_t XL = su + XT_L + brow;

        #pragma unroll
        for (int k = 0; k < 4; k++) {
            uint32_t ko = (uint32_t)(k * 32);
            uint32_t ah[2][4], al[2][4];
            ldsm4(AH + ko, ah[0]);
            ldsm4(AH + 2304 + ko, ah[1]);
            ldsm4(AL + ko, al[0]);
            ldsm4(AL + 2304 + ko, al[1]);
            uint32_t bh[7][2], bl[7][2];
            #pragma unroll
            for (int jj = 0; jj < 3; jj++) {
                ldsm4b(XH + b4_lane + jj * 2304 + ko, bh[2 * jj], bh[2 * jj + 1]);
                ldsm4b(XL + b4_lane + jj * 2304 + ko, bl[2 * jj], bl[2 * jj + 1]);
            }
            ldsm2(XH + b2_lane + 6912 + ko, bh[6]);
            ldsm2(XL + b2_lane + 6912 + ko, bl[6]);
            #pragma unroll
            for (int mt = 0; mt < 2; mt++)
                #pragma unroll
                for (int nt = 0; nt < 7; nt++) {
                    mma16816(acc[mt][nt], ah[mt], bh[nt]);
                    mma16816(acc[mt][nt], ah[mt], bl[nt]);
                    mma16816(acc[mt][nt], al[mt], bh[nt]);
                }
        }
        __syncthreads();
    }

    // ---- epilogue: regs -> smem (reuse Xt region) -> coalesced gmem ----
    float* s_out = (float*)smem;   // 128 x 112 f32 = 57344 B
    int q = lane >> 2, l = lane & 3;
    #pragma unroll
    for (int mt = 0; mt < 2; mt++)
        #pragma unroll
        for (int nt = 0; nt < 7; nt++) {
            int row = m_base + mt * 16 + q;
            int col = n_base + nt * 8 + l * 2;
            s_out[row * 112 + col] = acc[mt][nt][0];
            s_out[row * 112 + col + 1] = acc[mt][nt][1];
            s_out[(row + 8) * 112 + col] = acc[mt][nt][2];
            s_out[(row + 8) * 112 + col + 1] = acc[mt][nt][3];
        }
    __syncthreads();
    const float4* s4 = (const float4*)s_out;
    for (int i4 = tid; i4 < 128 * 28; i4 += 256) {
        int co = i4 / 28;
        int p4 = (i4 - co * 28) * 4;
        *(float4*)&out[((size_t)(b * Cch + co)) * HWs + t * 112 + p4] = s4[i4];
    }
}

extern "C" void kernel_launch(void* const* d_in, const int* in_sizes, int n_in,
                              void* d_out, int out_size) {
    const float* x      = (const float*)d_in[0];
    const float* w_mask = (const float*)d_in[1];
    const float* b_mask = (const float*)d_in[2];
    const float* w1     = (const float*)d_in[3];
    const float* b1     = (const float*)d_in[4];
    const float* ln_g   = (const float*)d_in[5];
    const float* ln_b   = (const float*)d_in[6];
    const float* w2     = (const float*)d_in[7];
    const float* b2     = (const float*)d_in[8];
    const float* w_fc   = (const float*)d_in[9];
    const float* b_fc   = (const float*)d_in[10];
    float* out = (float*)d_out;

    cudaFuncSetAttribute(conv_kernel, cudaFuncAttributeMaxDynamicSharedMemorySize, SMEM_TOTAL);

    mask_kernel<<<dim3(7, Bn), 448>>>(x, w_mask, b_mask);
    softmax_kernel<<<Bn, 1024>>>();
    ctx_kernel<<<dim3(8, Bn), 512>>>(x);
    transform_kernel<<<Bn, 256>>>(w1, b1, ln_g, ln_b, w2, b2);
    prepA_kernel<<<Bn * 18, 256>>>(w_fc, b_fc);
    conv_kernel<<<dim3(28, Bn), 256, SMEM_TOTAL>>>(x, out);
}

// round 5
// speedup vs baseline: 4.6181x; 1.0450x over previous
#include <cuda_runtime.h>
#include <cuda_bf16.h>
#include <math.h>
#include <stdint.h>

#define Bn 16
#define Cch 128
#define HWs 3136
#define Rr 16
#define MOc 256

// ---------------- device globals ----------------
__device__ float g_ctx[Bn * Cch];
__device__ float g_mask[Bn * HWs];
// per-(b,tap,chunk) weight tiles, plain row-major 128 cout x 64 cin bf16
__device__ __align__(16) __nv_bfloat16 g_wA_hi[16 * 18 * 8192];
__device__ __align__(16) __nv_bfloat16 g_wA_lo[16 * 18 * 8192];

// ---------------- PTX helpers (target-portable, sm_80+) ----------------
__device__ __forceinline__ uint32_t smem_u32(const void* p) {
    uint32_t a;
    asm("{ .reg .u64 t; cvta.to.shared.u64 t, %1; cvt.u32.u64 %0, t; }" : "=r"(a) : "l"(p));
    return a;
}
__device__ __forceinline__ void ldsm4(uint32_t a, uint32_t* r) {
    asm volatile("ldmatrix.sync.aligned.m8n8.x4.shared.b16 {%0,%1,%2,%3}, [%4];"
                 : "=r"(r[0]), "=r"(r[1]), "=r"(r[2]), "=r"(r[3]) : "r"(a));
}
__device__ __forceinline__ void ldsm4b(uint32_t a, uint32_t* r0, uint32_t* r1) {
    asm volatile("ldmatrix.sync.aligned.m8n8.x4.shared.b16 {%0,%1,%2,%3}, [%4];"
                 : "=r"(r0[0]), "=r"(r0[1]), "=r"(r1[0]), "=r"(r1[1]) : "r"(a));
}
__device__ __forceinline__ void ldsm2(uint32_t a, uint32_t* r) {
    asm volatile("ldmatrix.sync.aligned.m8n8.x2.shared.b16 {%0,%1}, [%2];"
                 : "=r"(r[0]), "=r"(r[1]) : "r"(a));
}
__device__ __forceinline__ void mma16816(float* c, const uint32_t* a, const uint32_t* b) {
    asm volatile("mma.sync.aligned.m16n8k16.row.col.f32.bf16.bf16.f32 "
                 "{%0,%1,%2,%3}, {%4,%5,%6,%7}, {%8,%9}, {%0,%1,%2,%3};"
                 : "+f"(c[0]), "+f"(c[1]), "+f"(c[2]), "+f"(c[3])
                 : "r"(a[0]), "r"(a[1]), "r"(a[2]), "r"(a[3]), "r"(b[0]), "r"(b[1]));
}
__device__ __forceinline__ void cp16(uint32_t dst, const void* src) {
    asm volatile("cp.async.cg.shared.global [%0], [%1], 16;" :: "r"(dst), "l"(src));
}
#define CP_COMMIT() asm volatile("cp.async.commit_group;" ::: "memory")
#define CP_WAIT1() asm volatile("cp.async.wait_group 1;" ::: "memory")
#define CP_WAIT0() asm volatile("cp.async.wait_group 0;" ::: "memory")

// ---------------- Kernel 1: mask[b,s] ----------------
__global__ void __launch_bounds__(448) mask_kernel(const float* __restrict__ x,
                                                   const float* __restrict__ w_mask,
                                                   const float* __restrict__ b_mask) {
    __shared__ float s_wm[Cch];
    int tid = threadIdx.x;
    int b = blockIdx.y;
    int s = blockIdx.x * 448 + tid;
    if (tid < Cch) s_wm[tid] = w_mask[tid];
    __syncthreads();
    const float* xb = x + (size_t)b * Cch * HWs + s;
    float m = 0.f;
    #pragma unroll 8
    for (int c = 0; c < Cch; c++) m = fmaf(xb[c * HWs], s_wm[c], m);
    g_mask[b * HWs + s] = m + b_mask[0];
}

// ---------------- Kernel 2: fused softmax + ctx ----------------
// grid (8 channel-groups, 16 batch), 512 threads. Each block redundantly
// computes the block-wide softmax of mask[b], then ctx for its 16 channels.
__global__ void __launch_bounds__(512) ctx_kernel(const float* __restrict__ x) {
    __shared__ float s_att[HWs];
    __shared__ float s_red[16];
    __shared__ float s_scalar;
    int tid = threadIdx.x;
    int b = blockIdx.y;
    int c_base = blockIdx.x * 16;
    const float* mb = g_mask + b * HWs;

    // load mask
    for (int i = tid; i < HWs; i += 512) s_att[i] = mb[i];
    __syncthreads();

    // block max
    float mx = -1e30f;
    for (int i = tid; i < HWs; i += 512) mx = fmaxf(mx, s_att[i]);
    #pragma unroll
    for (int o = 16; o > 0; o >>= 1) mx = fmaxf(mx, __shfl_xor_sync(0xffffffffu, mx, o));
    if ((tid & 31) == 0) s_red[tid >> 5] = mx;
    __syncthreads();
    if (tid < 32) {
        float v = (tid < 16) ? s_red[tid] : -1e30f;
        #pragma unroll
        for (int o = 8; o > 0; o >>= 1) v = fmaxf(v, __shfl_xor_sync(0xffffffffu, v, o));
        if (tid == 0) s_scalar = v;
    }
    __syncthreads();
    float gmax = s_scalar;

    // exp in place + block sum
    float sm = 0.f;
    for (int i = tid; i < HWs; i += 512) {
        float e = expf(s_att[i] - gmax);
        s_att[i] = e;
        sm += e;
    }
    #pragma unroll
    for (int o = 16; o > 0; o >>= 1) sm += __shfl_xor_sync(0xffffffffu, sm, o);
    if ((tid & 31) == 0) s_red[tid >> 5] = sm;
    __syncthreads();
    if (tid < 32) {
        float v = (tid < 16) ? s_red[tid] : 0.f;
        #pragma unroll
        for (int o = 8; o > 0; o >>= 1) v += __shfl_xor_sync(0xffffffffu, v, o);
        if (tid == 0) s_scalar = v;
    }
    __syncthreads();
    float inv = 1.f / s_scalar;

    // ctx: warp per channel
    int warp = tid >> 5, lane = tid & 31;
    int c = c_base + warp;
    const float* xc = x + ((size_t)b * Cch + c) * HWs;
    float p = 0.f;
    for (int s = lane; s < HWs; s += 32) p = fmaf(xc[s], s_att[s], p);
    p *= inv;
    #pragma unroll
    for (int o = 16; o > 0; o >>= 1) p += __shfl_xor_sync(0xffffffffu, p, o);
    if (lane == 0) g_ctx[b * Cch + c] = p;
}

// ---------------- Kernel 3: fused transform + weight-tile generation ----------------
// grid 16*18 blocks (b, tap, chunk), 256 threads. Each block redundantly
// computes the bottleneck transform (cheap) then its 128x64 hi/lo bf16 tile.
__global__ void __launch_bounds__(256) prep_kernel(const float* __restrict__ w1,
                                                   const float* __restrict__ b1,
                                                   const float* __restrict__ ln_g,
                                                   const float* __restrict__ ln_b,
                                                   const float* __restrict__ w2,
                                                   const float* __restrict__ b2,
                                                   const float* __restrict__ w_fc,
                                                   const float* __restrict__ b_fc) {
    __shared__ float s_ctx[Cch];
    __shared__ float s_t[Rr];
    __shared__ float s_a[128];
    int p = blockIdx.x;
    int b = p / 18;
    int rem = p - b * 18;
    int tap = rem >> 1;
    int chunk = rem & 1;
    int tid = threadIdx.x;

    if (tid < Cch) s_ctx[tid] = g_ctx[b * Cch + tid];
    __syncthreads();
    if (tid < Rr) {
        float acc = b1[tid];
        const float* wr = w1 + tid * Cch;
        #pragma unroll 16
        for (int c = 0; c < Cch; c++) acc = fmaf(s_ctx[c], wr[c], acc);
        s_t[tid] = acc;
    }
    __syncthreads();
    if (tid == 0) {
        float mu = 0.f;
        #pragma unroll
        for (int r = 0; r < Rr; r++) mu += s_t[r];
        mu *= (1.f / Rr);
        float var = 0.f;
        #pragma unroll
        for (int r = 0; r < Rr; r++) { float d = s_t[r] - mu; var = fmaf(d, d, var); }
        var *= (1.f / Rr);
        float invs = rsqrtf(var + 1e-5f);
        #pragma unroll
        for (int r = 0; r < Rr; r++) {
            float v = (s_t[r] - mu) * invs * ln_g[r] + ln_b[r];
            s_t[r] = fmaxf(v, 0.f);
        }
    }
    __syncthreads();
    if (tid < 128) {
        int row = 2 * tid + chunk;          // gate index for cout=tid, this chunk
        float acc = b2[row];
        const float* wr = w2 + row * Rr;
        #pragma unroll
        for (int r = 0; r < Rr; r++) acc = fmaf(s_t[r], wr[r], acc);
        s_a[tid] = 1.f / (1.f + expf(-acc));
    }
    __syncthreads();

    __nv_bfloat16* dh = g_wA_hi + (size_t)p * 8192;
    __nv_bfloat16* dl = g_wA_lo + (size_t)p * 8192;
    for (int e = tid; e < 8192; e += 256) {
        int co = e >> 6;
        int c = e & 63;
        int gidx = co * 1152 + (chunk * 64 + c) * 9 + tap;
        float w = fmaf(s_a[co], w_fc[gidx], b_fc[gidx]);
        __nv_bfloat16 hi = __float2bfloat16(w);
        __nv_bfloat16 lo = __float2bfloat16(w - __bfloat162float(hi));
        dh[e] = hi;
        dl[e] = lo;
    }
}

// ---------------- Kernel 4: HMMA implicit-GEMM conv, 512 threads ----------------
// grid (28 row-pair tiles, 16 batch), 16 warps (4/SMSP), 1 CTA/SM.
#define XT_H       0
#define XT_L       33408
#define A_BASE     66816
#define A_BUF_SZ   36864
#define SMEM_TOTAL 140544

__global__ void __launch_bounds__(512) conv_kernel(const float* __restrict__ x,
                                                   float* __restrict__ out) {
    extern __shared__ __align__(16) char smem[];
    uint32_t su = smem_u32(smem);
    int tid = threadIdx.x;
    int wid = tid >> 5;
    int lane = tid & 31;
    int t = blockIdx.x;
    int b = blockIdx.y;

    int grp = lane >> 3, lr = lane & 7;
    int m_base = (wid & 7) * 16;            // cout tile (M=16) for this warp
    int rr = wid >> 3;                      // output row within pair
    int n_base = rr * 56;

    uint32_t a_lane = (uint32_t)((((grp & 1) * 8 + lr) * 144) + ((grp >> 1) * 16));
    uint32_t b4_lane = (uint32_t)((((grp >> 1) * 8 + lr) * 144) + ((grp & 1) * 16));
    int l16 = lane & 15;
    uint32_t b2_lane = (uint32_t)(((l16 & 7) * 144) + (((l16 >> 3) & 1) * 16));

    float acc[7][4];
    #pragma unroll
    for (int nt = 0; nt < 7; nt++)
        #pragma unroll
        for (int e = 0; e < 4; e++) acc[nt][e] = 0.f;

    // issue A copy for s=0
    {
        const char* sh = (const char*)(g_wA_hi + (size_t)(b * 18 + 0) * 8192);
        const char* sl = (const char*)(g_wA_lo + (size_t)(b * 18 + 0) * 8192);
        uint32_t dh = su + A_BASE;
        for (int i = tid; i < 1024; i += 512) {
            uint32_t doff = (uint32_t)((i >> 3) * 144 + (i & 7) * 16);
            cp16(dh + doff, sh + i * 16);
            cp16(dh + 18432 + doff, sl + i * 16);
        }
        CP_COMMIT();
    }

    for (int s = 0; s < 18; s++) {
        int chunk = (s >= 9) ? 1 : 0;
        int tap = s - chunk * 9;
        int ky = tap / 3;
        int kx = tap - ky * 3;
        int buf = s & 1;

        if (s < 17) {
            int s1 = s + 1;
            int ch1 = (s1 >= 9) ? 1 : 0;
            int tp1 = s1 - ch1 * 9;
            const char* sh = (const char*)(g_wA_hi + (size_t)(b * 18 + tp1 * 2 + ch1) * 8192);
            const char* sl = (const char*)(g_wA_lo + (size_t)(b * 18 + tp1 * 2 + ch1) * 8192);
            uint32_t dh = su + A_BASE + (buf ^ 1) * A_BUF_SZ;
            for (int i = tid; i < 1024; i += 512) {
                uint32_t doff = (uint32_t)((i >> 3) * 144 + (i & 7) * 16);
                cp16(dh + doff, sh + i * 16);
                cp16(dh + 18432 + doff, sl + i * 16);
            }
            CP_COMMIT();
            CP_WAIT1();
        } else {
            CP_WAIT0();
        }

        if (tap == 0) {
            __nv_bfloat16* xh = (__nv_bfloat16*)(smem + XT_H);
            __nv_bfloat16* xl = (__nv_bfloat16*)(smem + XT_L);
            for (int i = tid; i < 64 * 232; i += 512) {
                int cin = i / 232;
                int j = i - cin * 232;
                int r = j / 58;
                int c = j - r * 58;
                int gy = 2 * t + r - 1;
                int gx = c - 1;
                float v = 0.f;
                if ((unsigned)gy < 56u && (unsigned)gx < 56u)
                    v = x[((size_t)(b * Cch + chunk * 64 + cin)) * HWs + gy * 56 + gx];
                __nv_bfloat16 hi = __float2bfloat16(v);
                __nv_bfloat16 lo = __float2bfloat16(v - __bfloat162float(hi));
                xh[j * 72 + cin] = hi;
                xl[j * 72 + cin] = lo;
            }
        }
        __syncthreads();

        uint32_t AH = su + A_BASE + buf * A_BUF_SZ + (uint32_t)(m_base * 144) + a_lane;
        uint32_t AL = AH + 18432;
        uint32_t brow = (uint32_t)(((rr + ky) * 58 + kx) * 144);
        uint32_t XH = su + XT_H + brow;
        uint32_t XL = su + XT_L + brow;

        #pragma unroll
        for (int k = 0; k < 4; k++) {
            uint32_t ko = (uint32_t)(k * 32);
            uint32_t ah[4], al[4];
            ldsm4(AH + ko, ah);
            ldsm4(AL + ko, al);
            uint32_t bh[7][2], bl[7][2];
            #pragma unroll
            for (int jj = 0; jj < 3; jj++) {
                ldsm4b(XH + b4_lane + jj * 2304 + ko, bh[2 * jj], bh[2 * jj + 1]);
                ldsm4b(XL + b4_lane + jj * 2304 + ko, bl[2 * jj], bl[2 * jj + 1]);
            }
            ldsm2(XH + b2_lane + 6912 + ko, bh[6]);
            ldsm2(XL + b2_lane + 6912 + ko, bl[6]);
            #pragma unroll
            for (int nt = 0; nt < 7; nt++) {
                mma16816(acc[nt], ah, bh[nt]);
                mma16816(acc[nt], ah, bl[nt]);
                mma16816(acc[nt], al, bh[nt]);
            }
        }
        __syncthreads();
    }

    // epilogue
    float* s_out = (float*)smem;   // 128 x 112 f32
    int q = lane >> 2, l = lane & 3;
    #pragma unroll
    for (int nt = 0; nt < 7; nt++) {
        int row = m_base + q;
        int col = n_base + nt * 8 + l * 2;
        s_out[row * 112 + col] = acc[nt][0];
        s_out[row * 112 + col + 1] = acc[nt][1];
        s_out[(row + 8) * 112 + col] = acc[nt][2];
        s_out[(row + 8) * 112 + col + 1] = acc[nt][3];
    }
    __syncthreads();
    const float4* s4 = (const float4*)s_out;
    for (int i4 = tid; i4 < 128 * 28; i4 += 512) {
        int co = i4 / 28;
        int p4 = (i4 - co * 28) * 4;
        *(float4*)&out[((size_t)(b * Cch + co)) * HWs + t * 112 + p4] = s4[i4];
    }
}

extern "C" void kernel_launch(void* const* d_in, const int* in_sizes, int n_in,
                              void* d_out, int out_size) {
    const float* x      = (const float*)d_in[0];
    const float* w_mask = (const float*)d_in[1];
    const float* b_mask = (const float*)d_in[2];
    const float* w1     = (const float*)d_in[3];
    const float* b1     = (const float*)d_in[4];
    const float* ln_g   = (const float*)d_in[5];
    const float* ln_b   = (const float*)d_in[6];
    const float* w2     = (const float*)d_in[7];
    const float* b2     = (const float*)d_in[8];
    const float* w_fc   = (const float*)d_in[9];
    const float* b_fc   = (const float*)d_in[10];
    float* out = (float*)d_out;

    cudaFuncSetAttribute(conv_kernel, cudaFuncAttributeMaxDynamicSharedMemorySize, SMEM_TOTAL);

    mask_kernel<<<dim3(7, Bn), 448>>>(x, w_mask, b_mask);
    ctx_kernel<<<dim3(8, Bn), 512>>>(x);
    prep_kernel<<<Bn * 18, 256>>>(w1, b1, ln_g, ln_b, w2, b2, w_fc, b_fc);
    conv_kernel<<<dim3(28, Bn), 512, SMEM_TOTAL>>>(x, out);
}